// round 2
// baseline (speedup 1.0000x reference)
#include <cuda_runtime.h>
#include <cuda_bf16.h>
#include <math.h>

// Problem dims
#define B_  2
#define S_  2048
#define D_  1024
#define H_  16
#define HD_ 64
#define BS_ (B_ * S_)   // 4096 rows

// Scratch (device globals — allocation-guard safe)
__device__ float g_q[B_ * H_ * S_ * HD_];   // [B,H,S,HD]
__device__ float g_k[B_ * H_ * S_ * HD_];
__device__ float g_v[B_ * H_ * S_ * HD_];
__device__ float g_wv[B_ * S_ * D_];        // [B,S,H*HD] concat layout

// ---------------------------------------------------------------------------
// QKV projection: per head, C[4096 x 64] = X[4096 x 1024] @ W_h[1024 x 64] + b
// grid: (row_tiles=64, heads=16, mat=3), 256 threads, 64x64x16 tiling, 4x4/thread
// ---------------------------------------------------------------------------
__global__ __launch_bounds__(256) void qkv_kernel(
    const float* __restrict__ x,
    const float* __restrict__ Wq, const float* __restrict__ bq,
    const float* __restrict__ Wk, const float* __restrict__ bk,
    const float* __restrict__ Wv, const float* __restrict__ bv)
{
    const int rt = blockIdx.x;       // row tile (64 rows of B*S)
    const int h  = blockIdx.y;       // head
    const int m  = blockIdx.z;       // 0=q 1=k 2=v

    const float* W    = (m == 0) ? Wq : (m == 1) ? Wk : Wv;
    const float* bias = (m == 0) ? bq : (m == 1) ? bk : bv;
    float*       out  = (m == 0) ? g_q : (m == 1) ? g_k : g_v;

    __shared__ float As[16][65];   // [k][row] transposed, padded
    __shared__ float Bs[16][64];   // [k][col]

    const int tid = threadIdx.x;
    const int tx = tid % 16;       // col group
    const int ty = tid / 16;       // row group
    const int row0 = rt * 64;

    const int la_row = tid >> 2;          // 0..63
    const int la_k4  = (tid & 3) * 4;     // 0,4,8,12
    const float* Wh = W + (size_t)h * D_ * HD_;

    float acc[4][4] = {};

    for (int k0 = 0; k0 < D_; k0 += 16) {
        // load A tile (64 rows x 16 k), transposed into As[k][row]
        float4 av = *(const float4*)&x[(size_t)(row0 + la_row) * D_ + k0 + la_k4];
        As[la_k4 + 0][la_row] = av.x;
        As[la_k4 + 1][la_row] = av.y;
        As[la_k4 + 2][la_row] = av.z;
        As[la_k4 + 3][la_row] = av.w;
        // load B tile (16 k x 64 cols), contiguous along cols
        {
            int bi = tid * 4;              // 0..1023
            int bk = bi >> 6, bn = bi & 63;
            *(float4*)&Bs[bk][bn] = *(const float4*)&Wh[(size_t)(k0 + bk) * HD_ + bn];
        }
        __syncthreads();
        #pragma unroll
        for (int kk = 0; kk < 16; kk++) {
            float a[4], b[4];
            #pragma unroll
            for (int r = 0; r < 4; r++) a[r] = As[kk][ty * 4 + r];
            #pragma unroll
            for (int c = 0; c < 4; c++) b[c] = Bs[kk][tx * 4 + c];
            #pragma unroll
            for (int r = 0; r < 4; r++)
                #pragma unroll
                for (int c = 0; c < 4; c++)
                    acc[r][c] += a[r] * b[c];
        }
        __syncthreads();
    }

    #pragma unroll
    for (int r = 0; r < 4; r++) {
        int row = row0 + ty * 4 + r;           // global row over B*S
        int b = row >> 11;                     // /2048
        int s = row & (S_ - 1);
        float* orow = out + (((size_t)b * H_ + h) * S_ + s) * HD_;
        #pragma unroll
        for (int c = 0; c < 4; c++)
            orow[tx * 4 + c] = acc[r][c] + bias[h * HD_ + tx * 4 + c];
    }
}

// ---------------------------------------------------------------------------
// Flash attention (causal): 128 queries per block, 1 query per thread.
// K/V tiles of 64 keys staged in smem; online softmax with lazy rescale.
// grid: (S/128 = 16, B*H = 32), 128 threads
// ---------------------------------------------------------------------------
__global__ __launch_bounds__(128) void attn_kernel()
{
    const int qt = blockIdx.x;
    const int bh = blockIdx.y;           // b*16 + h
    const int b  = bh >> 4;
    const int h  = bh & 15;
    const int tid = threadIdx.x;

    const float* Qb = g_q + (size_t)bh * S_ * HD_;
    const float* Kb = g_k + (size_t)bh * S_ * HD_;
    const float* Vb = g_v + (size_t)bh * S_ * HD_;

    __shared__ float4 Ks[64 * 16];
    __shared__ float4 Vs[64 * 16];

    const int qi = qt * 128 + tid;       // global query index in [0,S)
    float4 q4[16];
    #pragma unroll
    for (int e = 0; e < 16; e++)
        q4[e] = ((const float4*)(Qb + (size_t)qi * HD_))[e];

    float4 o4[16];
    #pragma unroll
    for (int e = 0; e < 16; e++) o4[e] = make_float4(0.f, 0.f, 0.f, 0.f);
    float mrun = -1e30f;
    float lrun = 0.f;
    const float scale = 0.125f;          // 1/sqrt(64)

    const int nkt = qt * 2 + 2;          // key tiles of 64 covering the causal range
    for (int kt = 0; kt < nkt; kt++) {
        __syncthreads();
        // stage K,V tile: 64 rows x 16 float4 = 1024 float4 each, 128 threads
        #pragma unroll
        for (int i = tid; i < 1024; i += 128) {
            Ks[i] = ((const float4*)(Kb + (size_t)kt * 64 * HD_))[i];
            Vs[i] = ((const float4*)(Vb + (size_t)kt * 64 * HD_))[i];
        }
        __syncthreads();

        int jmax = qi - kt * 64 + 1;     // number of unmasked keys in this tile
        if (jmax > 64) jmax = 64;
        for (int j = 0; j < jmax; j++) {
            float4 acc = make_float4(0.f, 0.f, 0.f, 0.f);
            #pragma unroll
            for (int e = 0; e < 16; e++) {
                float4 kv = Ks[j * 16 + e];
                float4 qv = q4[e];
                acc.x += qv.x * kv.x;
                acc.y += qv.y * kv.y;
                acc.z += qv.z * kv.z;
                acc.w += qv.w * kv.w;
            }
            float s = (acc.x + acc.y + acc.z + acc.w) * scale;
            float mn = fmaxf(mrun, s);
            float p = __expf(s - mn);
            if (s > mrun) {              // new max: rescale (rare after warmup)
                float corr = __expf(mrun - mn);
                lrun *= corr;
                #pragma unroll
                for (int e = 0; e < 16; e++) {
                    o4[e].x *= corr; o4[e].y *= corr;
                    o4[e].z *= corr; o4[e].w *= corr;
                }
                mrun = mn;
            }
            lrun += p;
            #pragma unroll
            for (int e = 0; e < 16; e++) {
                float4 vv = Vs[j * 16 + e];
                o4[e].x += p * vv.x;
                o4[e].y += p * vv.y;
                o4[e].z += p * vv.z;
                o4[e].w += p * vv.w;
            }
        }
    }

    const float inv_l = 1.f / lrun;
    // write concat layout [B,S,H,HD]
    float4* orow = (float4*)g_wv + (((size_t)b * S_ + qi) * H_ + h) * 16;
    #pragma unroll
    for (int e = 0; e < 16; e++) {
        float4 v = o4[e];
        v.x *= inv_l; v.y *= inv_l; v.z *= inv_l; v.w *= inv_l;
        orow[e] = v;
    }
}

// ---------------------------------------------------------------------------
// Output projection: out[4096 x 1024] = wv[4096 x 1024] @ Wo^T + bo
// out[r][d] = sum_c wv[r][c] * Wo[d][c]
// grid: (row_tiles=64, col_tiles=16), 256 threads, 64x64x16 tiling
// ---------------------------------------------------------------------------
__global__ __launch_bounds__(256) void oproj_kernel(
    const float* __restrict__ Wo, const float* __restrict__ bo,
    float* __restrict__ out)
{
    const int rt = blockIdx.x;
    const int ct = blockIdx.y;

    __shared__ float As[16][65];
    __shared__ float Bs[16][65];

    const int tid = threadIdx.x;
    const int tx = tid % 16;
    const int ty = tid / 16;
    const int row0 = rt * 64;
    const int col0 = ct * 64;

    const int la_row = tid >> 2;
    const int la_k4  = (tid & 3) * 4;

    float acc[4][4] = {};

    for (int k0 = 0; k0 < D_; k0 += 16) {
        float4 av = *(const float4*)&g_wv[(size_t)(row0 + la_row) * D_ + k0 + la_k4];
        As[la_k4 + 0][la_row] = av.x;
        As[la_k4 + 1][la_row] = av.y;
        As[la_k4 + 2][la_row] = av.z;
        As[la_k4 + 3][la_row] = av.w;
        // B tile: Bs[k][n] = Wo[(col0+n)*1024 + k0+k]
        {
            int n = tid >> 2;                 // 0..63
            float4 wv4 = *(const float4*)&Wo[(size_t)(col0 + n) * D_ + k0 + la_k4];
            Bs[la_k4 + 0][n] = wv4.x;
            Bs[la_k4 + 1][n] = wv4.y;
            Bs[la_k4 + 2][n] = wv4.z;
            Bs[la_k4 + 3][n] = wv4.w;
        }
        __syncthreads();
        #pragma unroll
        for (int kk = 0; kk < 16; kk++) {
            float a[4], bb[4];
            #pragma unroll
            for (int r = 0; r < 4; r++) a[r] = As[kk][ty * 4 + r];
            #pragma unroll
            for (int c = 0; c < 4; c++) bb[c] = Bs[kk][tx * 4 + c];
            #pragma unroll
            for (int r = 0; r < 4; r++)
                #pragma unroll
                for (int c = 0; c < 4; c++)
                    acc[r][c] += a[r] * bb[c];
        }
        __syncthreads();
    }

    #pragma unroll
    for (int r = 0; r < 4; r++) {
        int row = row0 + ty * 4 + r;
        #pragma unroll
        for (int c = 0; c < 4; c++) {
            int col = col0 + tx * 4 + c;
            out[(size_t)row * D_ + col] = acc[r][c] + bo[col];
        }
    }
}

// ---------------------------------------------------------------------------
// Launch. metadata order: x, Wq, bq, Wk, bk, Wv, bv, Wo, bo
// ---------------------------------------------------------------------------
extern "C" void kernel_launch(void* const* d_in, const int* in_sizes, int n_in,
                              void* d_out, int out_size)
{
    const float* x  = (const float*)d_in[0];
    const float* Wq = (const float*)d_in[1];
    const float* bq = (const float*)d_in[2];
    const float* Wk = (const float*)d_in[3];
    const float* bk = (const float*)d_in[4];
    const float* Wv = (const float*)d_in[5];
    const float* bv = (const float*)d_in[6];
    const float* Wo = (const float*)d_in[7];
    const float* bo = (const float*)d_in[8];
    float* out = (float*)d_out;

    dim3 g1(BS_ / 64, H_, 3);
    qkv_kernel<<<g1, 256>>>(x, Wq, bq, Wk, bk, Wv, bv);

    dim3 g2(S_ / 128, B_ * H_);
    attn_kernel<<<g2, 128>>>();

    dim3 g3(BS_ / 64, D_ / 64);
    oproj_kernel<<<g3, 256>>>(Wo, bo, out);
}

// round 3
// speedup vs baseline: 1.0206x; 1.0206x over previous
#include <cuda_runtime.h>
#include <cuda_bf16.h>
#include <math.h>

// Problem dims
#define B_  2
#define S_  2048
#define D_  1024
#define H_  16
#define HD_ 64
#define BS_ (B_ * S_)   // 4096 rows

typedef unsigned long long ull;

// Packed fp32x2 ops (FFMA2 path — ptxas never emits these from C++)
#define FMA2(acc, a, b) asm("fma.rn.f32x2 %0, %1, %2, %0;" : "+l"(acc) : "l"(a), "l"(b))
#define MUL2(d, a, b)   asm("mul.rn.f32x2 %0, %1, %2;" : "=l"(d) : "l"(a), "l"(b))
#define ADD2(d, a, b)   asm("add.rn.f32x2 %0, %1, %2;" : "=l"(d) : "l"(a), "l"(b))
#define PACK2(d, lo, hi) asm("mov.b64 %0, {%1, %2};" : "=l"(d) : "f"(lo), "f"(hi))
#define UNPACK2(lo, hi, s) asm("mov.b64 {%0, %1}, %2;" : "=f"(lo), "=f"(hi) : "l"(s))

union F4 { float4 v; ull u[2]; };

// Scratch (device globals — allocation-guard safe)
__device__ float g_q[B_ * H_ * S_ * HD_];   // [B,H,S,HD]
__device__ float g_k[B_ * H_ * S_ * HD_];
__device__ float g_v[B_ * H_ * S_ * HD_];
__device__ float g_wv[B_ * S_ * D_];        // [B,S,H*HD] concat layout

// ---------------------------------------------------------------------------
// QKV projection with f32x2: tile 128(M) x 128(N = 2 heads) x 16(K),
// 256 threads, 8x8 per thread via 32 FFMA2/kk.
// A tile stored DUPLICATED ({a,a} float2 pairs) so no per-iter packs needed.
// grid: (BS/128=32, H/2=8, mat=3)
// ---------------------------------------------------------------------------
__global__ __launch_bounds__(256, 2) void qkv_kernel(
    const float* __restrict__ x,
    const float* __restrict__ Wq, const float* __restrict__ bq,
    const float* __restrict__ Wk, const float* __restrict__ bk,
    const float* __restrict__ Wv, const float* __restrict__ bv)
{
    const int rt = blockIdx.x;       // row tile (128 rows of B*S)
    const int hp = blockIdx.y;       // head pair
    const int m  = blockIdx.z;       // 0=q 1=k 2=v

    const float* W    = (m == 0) ? Wq : (m == 1) ? Wk : Wv;
    const float* bias = (m == 0) ? bq : (m == 1) ? bk : bv;
    float*       out  = (m == 0) ? g_q : (m == 1) ? g_k : g_v;

    __shared__ float2 As2[16][130];  // duplicated A: As2[k][row] = {a,a}
    __shared__ float  Bs[16][128];   // Bs[k][n], n = head_local*64 + col

    const int tid = threadIdx.x;
    const int tx  = tid & 15;        // col group (8 cols)
    const int ty  = tid >> 4;        // row group (8 rows)
    const int row0 = rt * 128;
    const int h0   = hp * 2;

    ull acc2[8][4];
    #pragma unroll
    for (int r = 0; r < 8; r++)
        #pragma unroll
        for (int c = 0; c < 4; c++) acc2[r][c] = 0ULL;

    for (int k0 = 0; k0 < D_; k0 += 16) {
        // --- load A tile: 128 rows x 16 k, duplicated into As2[k][row] ---
        #pragma unroll
        for (int i = 0; i < 2; i++) {
            int idx = i * 256 + tid;          // 0..511
            int row = idx & 127;
            int kg  = idx >> 7;               // 0..3
            float4 v = *(const float4*)&x[(size_t)(row0 + row) * D_ + k0 + kg * 4];
            As2[kg * 4 + 0][row] = make_float2(v.x, v.x);
            As2[kg * 4 + 1][row] = make_float2(v.y, v.y);
            As2[kg * 4 + 2][row] = make_float2(v.z, v.z);
            As2[kg * 4 + 3][row] = make_float2(v.w, v.w);
        }
        // --- load B tile: 16 k x 128 n (two heads) ---
        #pragma unroll
        for (int i = 0; i < 2; i++) {
            int idx = i * 256 + tid;          // 0..511
            int k   = idx >> 5;               // 0..15
            int rem = idx & 31;
            int hl  = rem >> 4;               // 0..1
            int cg  = rem & 15;               // 0..15 (float4 groups of 64 cols)
            float4 v = *(const float4*)&W[((size_t)(h0 + hl) * D_ + (k0 + k)) * HD_ + cg * 4];
            *(float4*)&Bs[k][hl * 64 + cg * 4] = v;
        }
        __syncthreads();

        #pragma unroll
        for (int kk = 0; kk < 16; kk++) {
            ull a2[8];
            #pragma unroll
            for (int j = 0; j < 4; j++) {
                F4 t; t.v = *(const float4*)&As2[kk][ty * 8 + 2 * j];
                a2[2 * j]     = t.u[0];
                a2[2 * j + 1] = t.u[1];
            }
            ull b2[4];
            {
                F4 t0; t0.v = *(const float4*)&Bs[kk][tx * 8];
                F4 t1; t1.v = *(const float4*)&Bs[kk][tx * 8 + 4];
                b2[0] = t0.u[0]; b2[1] = t0.u[1];
                b2[2] = t1.u[0]; b2[3] = t1.u[1];
            }
            #pragma unroll
            for (int r = 0; r < 8; r++)
                #pragma unroll
                for (int c = 0; c < 4; c++)
                    FMA2(acc2[r][c], a2[r], b2[c]);
        }
        __syncthreads();
    }

    // epilogue: cols tx*8..tx*8+7 lie within one head (8 | 64)
    const int h  = h0 + (tx >> 3);
    const int c0 = (tx * 8) & 63;
    #pragma unroll
    for (int r = 0; r < 8; r++) {
        int row = row0 + ty * 8 + r;
        int b = row >> 11;                    // /2048
        int s = row & (S_ - 1);
        float* orow = out + (((size_t)b * H_ + h) * S_ + s) * HD_;
        #pragma unroll
        for (int c = 0; c < 4; c++) {
            float lo, hi;
            UNPACK2(lo, hi, acc2[r][c]);
            float2 o;
            o.x = lo + bias[h * HD_ + c0 + 2 * c];
            o.y = hi + bias[h * HD_ + c0 + 2 * c + 1];
            *(float2*)&orow[c0 + 2 * c] = o;
        }
    }
}

// ---------------------------------------------------------------------------
// Flash attention (causal) with f32x2: 128 queries/block, 1 query/thread.
// QK dot: 32 FFMA2 into 8 accumulators; PV: 32 FFMA2 with packed p.
// grid: (S/128 = 16, B*H = 32), 128 threads
// ---------------------------------------------------------------------------
__global__ __launch_bounds__(128) void attn_kernel()
{
    const int qt = blockIdx.x;
    const int bh = blockIdx.y;           // b*16 + h
    const int b  = bh >> 4;
    const int h  = bh & 15;
    const int tid = threadIdx.x;

    const float* Qb = g_q + (size_t)bh * S_ * HD_;
    const float* Kb = g_k + (size_t)bh * S_ * HD_;
    const float* Vb = g_v + (size_t)bh * S_ * HD_;

    __shared__ float4 Ks[64 * 16];
    __shared__ float4 Vs[64 * 16];

    const int qi = qt * 128 + tid;       // global query index
    F4 q[16];
    #pragma unroll
    for (int e = 0; e < 16; e++)
        q[e].v = ((const float4*)(Qb + (size_t)qi * HD_))[e];

    F4 o[16];
    #pragma unroll
    for (int e = 0; e < 16; e++) { o[e].u[0] = 0ULL; o[e].u[1] = 0ULL; }

    float mrun = -1e30f;
    float lrun = 0.f;
    const float scale = 0.125f;          // 1/sqrt(64)

    const int nkt = qt * 2 + 2;          // 64-key tiles covering causal range
    for (int kt = 0; kt < nkt; kt++) {
        __syncthreads();
        #pragma unroll
        for (int i = tid; i < 1024; i += 128) {
            Ks[i] = ((const float4*)(Kb + (size_t)kt * 64 * HD_))[i];
            Vs[i] = ((const float4*)(Vb + (size_t)kt * 64 * HD_))[i];
        }
        __syncthreads();

        int jmax = qi - kt * 64 + 1;
        if (jmax > 64) jmax = 64;
        for (int j = 0; j < jmax; j++) {
            ull acc[8];
            #pragma unroll
            for (int t = 0; t < 8; t++) acc[t] = 0ULL;
            #pragma unroll
            for (int e = 0; e < 16; e++) {
                F4 kv; kv.v = Ks[j * 16 + e];
                FMA2(acc[(2 * e) & 7],     q[e].u[0], kv.u[0]);
                FMA2(acc[(2 * e + 1) & 7], q[e].u[1], kv.u[1]);
            }
            ADD2(acc[0], acc[0], acc[4]);
            ADD2(acc[1], acc[1], acc[5]);
            ADD2(acc[2], acc[2], acc[6]);
            ADD2(acc[3], acc[3], acc[7]);
            ADD2(acc[0], acc[0], acc[2]);
            ADD2(acc[1], acc[1], acc[3]);
            ADD2(acc[0], acc[0], acc[1]);
            float slo, shi;
            UNPACK2(slo, shi, acc[0]);
            float s = (slo + shi) * scale;

            float mn = fmaxf(mrun, s);
            float p = __expf(s - mn);
            if (s > mrun) {              // new max: rescale (rare)
                float corr = __expf(mrun - mn);
                lrun *= corr;
                ull corr2; PACK2(corr2, corr, corr);
                #pragma unroll
                for (int e = 0; e < 16; e++) {
                    MUL2(o[e].u[0], o[e].u[0], corr2);
                    MUL2(o[e].u[1], o[e].u[1], corr2);
                }
                mrun = mn;
            }
            lrun += p;
            ull p2; PACK2(p2, p, p);
            #pragma unroll
            for (int e = 0; e < 16; e++) {
                F4 vv; vv.v = Vs[j * 16 + e];
                FMA2(o[e].u[0], p2, vv.u[0]);
                FMA2(o[e].u[1], p2, vv.u[1]);
            }
        }
    }

    const float inv_l = 1.f / lrun;
    ull il2; PACK2(il2, inv_l, inv_l);
    float4* orow = (float4*)g_wv + (((size_t)b * S_ + qi) * H_ + h) * 16;
    #pragma unroll
    for (int e = 0; e < 16; e++) {
        MUL2(o[e].u[0], o[e].u[0], il2);
        MUL2(o[e].u[1], o[e].u[1], il2);
        orow[e] = o[e].v;
    }
}

// ---------------------------------------------------------------------------
// Output projection with f32x2: out[4096 x 1024] = wv @ Wo^T + bo
// tile 128x128x16, 256 threads, 8x8/thread. grid: (32, 8)
// ---------------------------------------------------------------------------
__global__ __launch_bounds__(256, 2) void oproj_kernel(
    const float* __restrict__ Wo, const float* __restrict__ bo,
    float* __restrict__ out)
{
    const int rt = blockIdx.x;
    const int ct = blockIdx.y;

    __shared__ float2 As2[16][130];  // duplicated A
    __shared__ float  Bs[16][128];   // Bs[k][n] = Wo[(col0+n)][k0+k]

    const int tid = threadIdx.x;
    const int tx  = tid & 15;
    const int ty  = tid >> 4;
    const int row0 = rt * 128;
    const int col0 = ct * 128;

    ull acc2[8][4];
    #pragma unroll
    for (int r = 0; r < 8; r++)
        #pragma unroll
        for (int c = 0; c < 4; c++) acc2[r][c] = 0ULL;

    for (int k0 = 0; k0 < D_; k0 += 16) {
        #pragma unroll
        for (int i = 0; i < 2; i++) {
            int idx = i * 256 + tid;
            int row = idx & 127;
            int kg  = idx >> 7;
            float4 v = *(const float4*)&g_wv[(size_t)(row0 + row) * D_ + k0 + kg * 4];
            As2[kg * 4 + 0][row] = make_float2(v.x, v.x);
            As2[kg * 4 + 1][row] = make_float2(v.y, v.y);
            As2[kg * 4 + 2][row] = make_float2(v.z, v.z);
            As2[kg * 4 + 3][row] = make_float2(v.w, v.w);
        }
        // B tile: transpose load, Bs[k][n] = Wo[(col0+n)*D + k0+k]
        #pragma unroll
        for (int i = 0; i < 2; i++) {
            int idx = i * 256 + tid;
            int n   = idx & 127;
            int kg  = idx >> 7;
            float4 v = *(const float4*)&Wo[(size_t)(col0 + n) * D_ + k0 + kg * 4];
            Bs[kg * 4 + 0][n] = v.x;
            Bs[kg * 4 + 1][n] = v.y;
            Bs[kg * 4 + 2][n] = v.z;
            Bs[kg * 4 + 3][n] = v.w;
        }
        __syncthreads();

        #pragma unroll
        for (int kk = 0; kk < 16; kk++) {
            ull a2[8];
            #pragma unroll
            for (int j = 0; j < 4; j++) {
                F4 t; t.v = *(const float4*)&As2[kk][ty * 8 + 2 * j];
                a2[2 * j]     = t.u[0];
                a2[2 * j + 1] = t.u[1];
            }
            ull b2[4];
            {
                F4 t0; t0.v = *(const float4*)&Bs[kk][tx * 8];
                F4 t1; t1.v = *(const float4*)&Bs[kk][tx * 8 + 4];
                b2[0] = t0.u[0]; b2[1] = t0.u[1];
                b2[2] = t1.u[0]; b2[3] = t1.u[1];
            }
            #pragma unroll
            for (int r = 0; r < 8; r++)
                #pragma unroll
                for (int c = 0; c < 4; c++)
                    FMA2(acc2[r][c], a2[r], b2[c]);
        }
        __syncthreads();
    }

    #pragma unroll
    for (int r = 0; r < 8; r++) {
        int row = row0 + ty * 8 + r;
        #pragma unroll
        for (int c = 0; c < 4; c++) {
            int col = col0 + tx * 8 + 2 * c;
            float lo, hi;
            UNPACK2(lo, hi, acc2[r][c]);
            float2 o;
            o.x = lo + bo[col];
            o.y = hi + bo[col + 1];
            *(float2*)&out[(size_t)row * D_ + col] = o;
        }
    }
}

// ---------------------------------------------------------------------------
// Launch. metadata order: x, Wq, bq, Wk, bk, Wv, bv, Wo, bo
// ---------------------------------------------------------------------------
extern "C" void kernel_launch(void* const* d_in, const int* in_sizes, int n_in,
                              void* d_out, int out_size)
{
    const float* x  = (const float*)d_in[0];
    const float* Wq = (const float*)d_in[1];
    const float* bq = (const float*)d_in[2];
    const float* Wk = (const float*)d_in[3];
    const float* bk = (const float*)d_in[4];
    const float* Wv = (const float*)d_in[5];
    const float* bv = (const float*)d_in[6];
    const float* Wo = (const float*)d_in[7];
    const float* bo = (const float*)d_in[8];
    float* out = (float*)d_out;

    dim3 g1(BS_ / 128, H_ / 2, 3);
    qkv_kernel<<<g1, 256>>>(x, Wq, bq, Wk, bk, Wv, bv);

    dim3 g2(S_ / 128, B_ * H_);
    attn_kernel<<<g2, 128>>>();

    dim3 g3(BS_ / 128, D_ / 128);
    oproj_kernel<<<g3, 256>>>(Wo, bo, out);
}

// round 4
// speedup vs baseline: 3.1198x; 3.0569x over previous
#include <cuda_runtime.h>
#include <stdint.h>
#include <math.h>

// Problem dims
#define B_  2
#define S_  2048
#define D_  1024
#define H_  16
#define HD_ 64
#define BS_ (B_ * S_)   // 4096

// Scratch (device globals — allocation-guard safe)
__device__ float g_q[B_ * H_ * S_ * HD_];   // [B,H,S,HD]
__device__ float g_k[B_ * H_ * S_ * HD_];
__device__ float g_v[B_ * H_ * S_ * HD_];
__device__ float g_wv[B_ * S_ * D_];        // [B,S,H*HD]

__device__ __forceinline__ uint32_t f2tf(float f) {
    uint32_t u;
    asm("cvt.rna.tf32.f32 %0, %1;" : "=r"(u) : "f"(f));
    return u;
}

__device__ __forceinline__ void mma_tf32(float c[4], const uint32_t a[4],
                                         uint32_t b0, uint32_t b1) {
    asm volatile(
        "mma.sync.aligned.m16n8k8.row.col.f32.tf32.tf32.f32 "
        "{%0,%1,%2,%3}, {%4,%5,%6,%7}, {%8,%9}, {%0,%1,%2,%3};"
        : "+f"(c[0]), "+f"(c[1]), "+f"(c[2]), "+f"(c[3])
        : "r"(a[0]), "r"(a[1]), "r"(a[2]), "r"(a[3]), "r"(b0), "r"(b1));
}

// ---------------------------------------------------------------------------
// QKV projection, tf32 MMA. C[4096 x 128] per (head-pair, mat).
// Block 128x128x(K-chunk 32), 8 warps, warp tile 64x32.
// smem strides 36 (== 4 mod 32): conflict-free fragment gathers.
// grid: (BS/128=32, H/2=8, 3), 256 threads
// ---------------------------------------------------------------------------
__global__ __launch_bounds__(256, 2) void qkv_kernel(
    const float* __restrict__ x,
    const float* __restrict__ Wq, const float* __restrict__ bq,
    const float* __restrict__ Wk, const float* __restrict__ bk,
    const float* __restrict__ Wv, const float* __restrict__ bv)
{
    const int rt = blockIdx.x;
    const int hp = blockIdx.y;
    const int m  = blockIdx.z;

    const float* W    = (m == 0) ? Wq : (m == 1) ? Wk : Wv;
    const float* bias = (m == 0) ? bq : (m == 1) ? bk : bv;
    float*       out  = (m == 0) ? g_q : (m == 1) ? g_k : g_v;

    __shared__ uint32_t sA[128 * 36];   // [row][k], stride 36
    __shared__ uint32_t sB[128 * 36];   // [n][k],   stride 36

    const int tid  = threadIdx.x;
    const int wid  = tid >> 5;
    const int lane = tid & 31;
    const int wm   = wid >> 2;          // 0..1
    const int wn   = wid & 3;           // 0..3
    const int row0 = rt * 128;
    const int h0   = hp * 2;

    float acc[4][4][4];
    #pragma unroll
    for (int mi = 0; mi < 4; mi++)
        #pragma unroll
        for (int ni = 0; ni < 4; ni++)
            #pragma unroll
            for (int c = 0; c < 4; c++) acc[mi][ni][c] = 0.f;

    for (int k0 = 0; k0 < D_; k0 += 32) {
        // stage A: 128 rows x 32 k
        #pragma unroll
        for (int i = 0; i < 4; i++) {
            int g = i * 256 + tid;            // 0..1023 float4 units
            int row = g >> 3;
            int kg  = (g & 7) * 4;
            float4 v = *(const float4*)&x[(size_t)(row0 + row) * D_ + k0 + kg];
            uint32_t* d = &sA[row * 36 + kg];
            d[0] = f2tf(v.x); d[1] = f2tf(v.y); d[2] = f2tf(v.z); d[3] = f2tf(v.w);
        }
        // stage B: [n][k] from W[h][k][e], n = hl*64+e
        #pragma unroll
        for (int i = 0; i < 4; i++) {
            int g  = i * 256 + tid;           // 0..1023
            int k  = g >> 5;                  // 0..31
            int n0 = (g & 31) * 4;            // 0..124
            float4 v = *(const float4*)&W[((size_t)(h0 + (n0 >> 6)) * D_ + (k0 + k)) * HD_ + (n0 & 63)];
            sB[(n0 + 0) * 36 + k] = f2tf(v.x);
            sB[(n0 + 1) * 36 + k] = f2tf(v.y);
            sB[(n0 + 2) * 36 + k] = f2tf(v.z);
            sB[(n0 + 3) * 36 + k] = f2tf(v.w);
        }
        __syncthreads();

        #pragma unroll
        for (int kk = 0; kk < 4; kk++) {
            const int kc = kk * 8 + (lane & 3);
            uint32_t a[4][4], b[4][2];
            #pragma unroll
            for (int mi = 0; mi < 4; mi++) {
                int r = (wm * 64 + mi * 16 + (lane >> 2)) * 36;
                a[mi][0] = sA[r + kc];
                a[mi][1] = sA[r + 8 * 36 + kc];
                a[mi][2] = sA[r + kc + 4];
                a[mi][3] = sA[r + 8 * 36 + kc + 4];
            }
            #pragma unroll
            for (int ni = 0; ni < 4; ni++) {
                int r = (wn * 32 + ni * 8 + (lane >> 2)) * 36;
                b[ni][0] = sB[r + kc];
                b[ni][1] = sB[r + kc + 4];
            }
            #pragma unroll
            for (int mi = 0; mi < 4; mi++)
                #pragma unroll
                for (int ni = 0; ni < 4; ni++)
                    mma_tf32(acc[mi][ni], a[mi], b[ni][0], b[ni][1]);
        }
        __syncthreads();
    }

    // epilogue: out layout [B,H,S,HD]
    #pragma unroll
    for (int mi = 0; mi < 4; mi++) {
        int rl  = wm * 64 + mi * 16 + (lane >> 2);
        int row = row0 + rl;
        int bb  = row >> 11;
        int s   = row & (S_ - 1);
        #pragma unroll
        for (int ni = 0; ni < 4; ni++) {
            int cl = wn * 32 + ni * 8 + 2 * (lane & 3);
            int h  = h0 + (cl >> 6);
            int e  = cl & 63;
            float bv0 = bias[h * HD_ + e];
            float bv1 = bias[h * HD_ + e + 1];
            float* p0 = out + (((size_t)bb * H_ + h) * S_ + s) * HD_ + e;
            float* p1 = out + (((size_t)bb * H_ + h) * S_ + s + 8) * HD_ + e;
            float2 o0 = make_float2(acc[mi][ni][0] + bv0, acc[mi][ni][1] + bv1);
            float2 o1 = make_float2(acc[mi][ni][2] + bv0, acc[mi][ni][3] + bv1);
            *(float2*)p0 = o0;
            *(float2*)p1 = o1;
        }
    }
}

// ---------------------------------------------------------------------------
// Flash attention (causal), tf32 MMA. Block = 64 queries, 4 warps x 16 rows.
// K tiles of 64 keys. Scores in fragments; online softmax via quad shuffles.
// P round-trips through smem (overlaying K buffer) for the PV A-operand.
// grid: (S/64 = 32 query tiles [reversed], B*H = 32), 128 threads
// ---------------------------------------------------------------------------
__global__ __launch_bounds__(128, 4) void attn_kernel()
{
    const int qt = 31 - blockIdx.x;      // big blocks first
    const int bh = blockIdx.y;
    const int b  = bh >> 4;
    const int h  = bh & 15;
    const int tid  = threadIdx.x;
    const int w    = tid >> 5;
    const int lane = tid & 31;
    const int qr   = lane >> 2;          // 0..7
    const int ql   = lane & 3;           // 0..3

    const float* Qb = g_q + (size_t)bh * S_ * HD_;
    const float* Kb = g_k + (size_t)bh * S_ * HD_;
    const float* Vb = g_v + (size_t)bh * S_ * HD_;

    __shared__ uint32_t sKP[64 * 68];    // K tile [key][hd] / P [qrow][key] / Q staging
    __shared__ uint32_t sV[64 * 72];     // V tile [key][hd]

    // ---- stage Q (scaled by 1/8), extract A fragments ----
    #pragma unroll
    for (int i = 0; i < 8; i++) {
        int g = i * 128 + tid;           // 0..1023 float4 units
        int row = g >> 4;
        int c4  = (g & 15) * 4;
        float4 v = *(const float4*)&Qb[(size_t)(qt * 64 + row) * HD_ + c4];
        uint32_t* d = &sKP[row * 68 + c4];
        d[0] = f2tf(v.x * 0.125f); d[1] = f2tf(v.y * 0.125f);
        d[2] = f2tf(v.z * 0.125f); d[3] = f2tf(v.w * 0.125f);
    }
    __syncthreads();

    uint32_t qa[8][4];
    #pragma unroll
    for (int kk = 0; kk < 8; kk++) {
        int r = (w * 16 + qr) * 68;
        int kc = kk * 8 + ql;
        qa[kk][0] = sKP[r + kc];
        qa[kk][1] = sKP[r + 8 * 68 + kc];
        qa[kk][2] = sKP[r + kc + 4];
        qa[kk][3] = sKP[r + 8 * 68 + kc + 4];
    }

    float O[8][4];
    #pragma unroll
    for (int n = 0; n < 8; n++)
        #pragma unroll
        for (int c = 0; c < 4; c++) O[n][c] = 0.f;
    float m0 = -1e30f, m1 = -1e30f, l0 = 0.f, l1 = 0.f;

    for (int kt = 0; kt <= qt; kt++) {
        __syncthreads();                 // done reading sKP (Q frags / prev P)
        const int j0 = kt * 64;
        // stage K and V tiles
        #pragma unroll
        for (int i = 0; i < 8; i++) {
            int g = i * 128 + tid;
            int row = g >> 4;
            int c4  = (g & 15) * 4;
            float4 kv = *(const float4*)&Kb[(size_t)(j0 + row) * HD_ + c4];
            uint32_t* dk = &sKP[row * 68 + c4];
            dk[0] = f2tf(kv.x); dk[1] = f2tf(kv.y); dk[2] = f2tf(kv.z); dk[3] = f2tf(kv.w);
            float4 vv = *(const float4*)&Vb[(size_t)(j0 + row) * HD_ + c4];
            uint32_t* dv = &sV[row * 68 + c4 + row * 4];  // stride 72 = 68+4
            dv[0] = f2tf(vv.x); dv[1] = f2tf(vv.y); dv[2] = f2tf(vv.z); dv[3] = f2tf(vv.w);
        }
        __syncthreads();

        // ---- QK^T: scores 16x64 per warp ----
        float sc[8][4];
        #pragma unroll
        for (int n = 0; n < 8; n++)
            #pragma unroll
            for (int c = 0; c < 4; c++) sc[n][c] = 0.f;
        #pragma unroll
        for (int kk = 0; kk < 8; kk++) {
            const int kc = kk * 8 + ql;
            #pragma unroll
            for (int n = 0; n < 8; n++) {
                int r = (n * 8 + qr) * 68;
                mma_tf32(sc[n], qa[kk], sKP[r + kc], sKP[r + kc + 4]);
            }
        }

        // causal mask (only the diagonal tile needs it)
        if (kt == qt) {
            const int r0 = w * 16 + qr;
            #pragma unroll
            for (int n = 0; n < 8; n++) {
                int c = n * 8 + 2 * ql;
                if (c     > r0)     sc[n][0] = -1e30f;
                if (c + 1 > r0)     sc[n][1] = -1e30f;
                if (c     > r0 + 8) sc[n][2] = -1e30f;
                if (c + 1 > r0 + 8) sc[n][3] = -1e30f;
            }
        }

        // ---- online softmax on fragments ----
        float mt0 = -1e30f, mt1 = -1e30f;
        #pragma unroll
        for (int n = 0; n < 8; n++) {
            mt0 = fmaxf(mt0, fmaxf(sc[n][0], sc[n][1]));
            mt1 = fmaxf(mt1, fmaxf(sc[n][2], sc[n][3]));
        }
        mt0 = fmaxf(mt0, __shfl_xor_sync(0xffffffffu, mt0, 1));
        mt0 = fmaxf(mt0, __shfl_xor_sync(0xffffffffu, mt0, 2));
        mt1 = fmaxf(mt1, __shfl_xor_sync(0xffffffffu, mt1, 1));
        mt1 = fmaxf(mt1, __shfl_xor_sync(0xffffffffu, mt1, 2));
        float mn0 = fmaxf(m0, mt0), mn1 = fmaxf(m1, mt1);
        float cr0 = __expf(m0 - mn0), cr1 = __expf(m1 - mn1);
        m0 = mn0; m1 = mn1;
        #pragma unroll
        for (int n = 0; n < 8; n++) {
            O[n][0] *= cr0; O[n][1] *= cr0;
            O[n][2] *= cr1; O[n][3] *= cr1;
        }
        float s0 = 0.f, s1 = 0.f;
        #pragma unroll
        for (int n = 0; n < 8; n++) {
            sc[n][0] = __expf(sc[n][0] - mn0);
            sc[n][1] = __expf(sc[n][1] - mn0);
            sc[n][2] = __expf(sc[n][2] - mn1);
            sc[n][3] = __expf(sc[n][3] - mn1);
            s0 += sc[n][0] + sc[n][1];
            s1 += sc[n][2] + sc[n][3];
        }
        s0 += __shfl_xor_sync(0xffffffffu, s0, 1);
        s0 += __shfl_xor_sync(0xffffffffu, s0, 2);
        s1 += __shfl_xor_sync(0xffffffffu, s1, 1);
        s1 += __shfl_xor_sync(0xffffffffu, s1, 2);
        l0 = l0 * cr0 + s0;
        l1 = l1 * cr1 + s1;

        __syncthreads();                 // all warps done reading K
        // write P into sKP (each warp writes only its own 16 rows)
        #pragma unroll
        for (int n = 0; n < 8; n++) {
            int c = n * 8 + 2 * ql;
            uint32_t* d0 = &sKP[(w * 16 + qr) * 68 + c];
            uint32_t* d1 = &sKP[(w * 16 + qr + 8) * 68 + c];
            d0[0] = f2tf(sc[n][0]); d0[1] = f2tf(sc[n][1]);
            d1[0] = f2tf(sc[n][2]); d1[1] = f2tf(sc[n][3]);
        }
        __syncwarp();                    // warp-local: PV reads only own rows

        // ---- P @ V -> O ----
        #pragma unroll
        for (int kk = 0; kk < 8; kk++) {
            uint32_t pa[4];
            int r = (w * 16 + qr) * 68;
            int kc = kk * 8 + ql;
            pa[0] = sKP[r + kc];
            pa[1] = sKP[r + 8 * 68 + kc];
            pa[2] = sKP[r + kc + 4];
            pa[3] = sKP[r + 8 * 68 + kc + 4];
            #pragma unroll
            for (int n = 0; n < 8; n++) {
                int vb = (kk * 8 + ql) * 72 + n * 8 + qr;
                mma_tf32(O[n], pa, sV[vb], sV[vb + 4 * 72]);
            }
        }
    }

    // ---- normalize + store to g_wv [B,S,H*HD] ----
    float inv0 = 1.f / l0, inv1 = 1.f / l1;
    int r0g = qt * 64 + w * 16 + qr;
    float* base0 = g_wv + ((size_t)b * S_ + r0g) * D_ + h * HD_;
    float* base1 = g_wv + ((size_t)b * S_ + r0g + 8) * D_ + h * HD_;
    #pragma unroll
    for (int n = 0; n < 8; n++) {
        int c = n * 8 + 2 * ql;
        *(float2*)&base0[c] = make_float2(O[n][0] * inv0, O[n][1] * inv0);
        *(float2*)&base1[c] = make_float2(O[n][2] * inv1, O[n][3] * inv1);
    }
}

// ---------------------------------------------------------------------------
// Output projection, tf32 MMA: out = g_wv @ Wo^T + bo.  Same skeleton as qkv.
// grid: (32, 8), 256 threads
// ---------------------------------------------------------------------------
__global__ __launch_bounds__(256, 2) void oproj_kernel(
    const float* __restrict__ Wo, const float* __restrict__ bo,
    float* __restrict__ out)
{
    const int rt = blockIdx.x;
    const int ct = blockIdx.y;

    __shared__ uint32_t sA[128 * 36];
    __shared__ uint32_t sB[128 * 36];

    const int tid  = threadIdx.x;
    const int wid  = tid >> 5;
    const int lane = tid & 31;
    const int wm   = wid >> 2;
    const int wn   = wid & 3;
    const int row0 = rt * 128;
    const int col0 = ct * 128;

    float acc[4][4][4];
    #pragma unroll
    for (int mi = 0; mi < 4; mi++)
        #pragma unroll
        for (int ni = 0; ni < 4; ni++)
            #pragma unroll
            for (int c = 0; c < 4; c++) acc[mi][ni][c] = 0.f;

    for (int k0 = 0; k0 < D_; k0 += 32) {
        #pragma unroll
        for (int i = 0; i < 4; i++) {
            int g = i * 256 + tid;
            int row = g >> 3;
            int kg  = (g & 7) * 4;
            float4 v = *(const float4*)&g_wv[(size_t)(row0 + row) * D_ + k0 + kg];
            uint32_t* d = &sA[row * 36 + kg];
            d[0] = f2tf(v.x); d[1] = f2tf(v.y); d[2] = f2tf(v.z); d[3] = f2tf(v.w);
        }
        #pragma unroll
        for (int i = 0; i < 4; i++) {
            int g = i * 256 + tid;
            int n  = g >> 3;
            int kg = (g & 7) * 4;
            float4 v = *(const float4*)&Wo[(size_t)(col0 + n) * D_ + k0 + kg];
            uint32_t* d = &sB[n * 36 + kg];
            d[0] = f2tf(v.x); d[1] = f2tf(v.y); d[2] = f2tf(v.z); d[3] = f2tf(v.w);
        }
        __syncthreads();

        #pragma unroll
        for (int kk = 0; kk < 4; kk++) {
            const int kc = kk * 8 + (lane & 3);
            uint32_t a[4][4], b[4][2];
            #pragma unroll
            for (int mi = 0; mi < 4; mi++) {
                int r = (wm * 64 + mi * 16 + (lane >> 2)) * 36;
                a[mi][0] = sA[r + kc];
                a[mi][1] = sA[r + 8 * 36 + kc];
                a[mi][2] = sA[r + kc + 4];
                a[mi][3] = sA[r + 8 * 36 + kc + 4];
            }
            #pragma unroll
            for (int ni = 0; ni < 4; ni++) {
                int r = (wn * 32 + ni * 8 + (lane >> 2)) * 36;
                b[ni][0] = sB[r + kc];
                b[ni][1] = sB[r + kc + 4];
            }
            #pragma unroll
            for (int mi = 0; mi < 4; mi++)
                #pragma unroll
                for (int ni = 0; ni < 4; ni++)
                    mma_tf32(acc[mi][ni], a[mi], b[ni][0], b[ni][1]);
        }
        __syncthreads();
    }

    #pragma unroll
    for (int mi = 0; mi < 4; mi++) {
        int row = row0 + wm * 64 + mi * 16 + (lane >> 2);
        #pragma unroll
        for (int ni = 0; ni < 4; ni++) {
            int col = col0 + wn * 32 + ni * 8 + 2 * (lane & 3);
            float bv0 = bo[col], bv1 = bo[col + 1];
            *(float2*)&out[(size_t)row * D_ + col] =
                make_float2(acc[mi][ni][0] + bv0, acc[mi][ni][1] + bv1);
            *(float2*)&out[(size_t)(row + 8) * D_ + col] =
                make_float2(acc[mi][ni][2] + bv0, acc[mi][ni][3] + bv1);
        }
    }
}

// ---------------------------------------------------------------------------
// Launch. metadata order: x, Wq, bq, Wk, bk, Wv, bv, Wo, bo
// ---------------------------------------------------------------------------
extern "C" void kernel_launch(void* const* d_in, const int* in_sizes, int n_in,
                              void* d_out, int out_size)
{
    const float* x  = (const float*)d_in[0];
    const float* Wq = (const float*)d_in[1];
    const float* bq = (const float*)d_in[2];
    const float* Wk = (const float*)d_in[3];
    const float* bk = (const float*)d_in[4];
    const float* Wv = (const float*)d_in[5];
    const float* bv = (const float*)d_in[6];
    const float* Wo = (const float*)d_in[7];
    const float* bo = (const float*)d_in[8];
    float* out = (float*)d_out;

    dim3 g1(BS_ / 128, H_ / 2, 3);
    qkv_kernel<<<g1, 256>>>(x, Wq, bq, Wk, bk, Wv, bv);

    dim3 g2(S_ / 64, B_ * H_);
    attn_kernel<<<g2, 128>>>();

    dim3 g3(BS_ / 128, D_ / 128);
    oproj_kernel<<<g3, 256>>>(Wo, bo, out);
}

// round 5
// speedup vs baseline: 4.3376x; 1.3903x over previous
#include <cuda_runtime.h>
#include <stdint.h>

// Problem dims
#define B_  2
#define S_  2048
#define D_  1024
#define H_  16
#define HD_ 64
#define BS_ (B_ * S_)         // 4096
#define NX  (BS_ * D_)        // 4194304
#define NW  (H_ * D_ * HD_)   // 1048576

// tf32-bit scratch (device globals — allocation-guard safe)
__device__ uint32_t g_xt[NX];
__device__ uint32_t g_wqt[NW], g_wkt[NW], g_wvt[NW], g_wot[D_ * D_];
__device__ float    g_bqs[H_ * HD_];
__device__ uint32_t g_q[B_ * H_ * S_ * HD_];   // pre-scaled by 1/8
__device__ uint32_t g_k[B_ * H_ * S_ * HD_];
__device__ uint32_t g_v[B_ * H_ * S_ * HD_];
__device__ uint32_t g_wv[BS_ * D_];            // [B,S,H*HD] tf32 bits

__device__ __forceinline__ uint32_t f2tf(float f) {
    uint32_t u;
    asm("cvt.rna.tf32.f32 %0, %1;" : "=r"(u) : "f"(f));
    return u;
}

__device__ __forceinline__ void mma_tf32(float c[4], const uint32_t a[4],
                                         uint32_t b0, uint32_t b1) {
    asm volatile(
        "mma.sync.aligned.m16n8k8.row.col.f32.tf32.tf32.f32 "
        "{%0,%1,%2,%3}, {%4,%5,%6,%7}, {%8,%9}, {%0,%1,%2,%3};"
        : "+f"(c[0]), "+f"(c[1]), "+f"(c[2]), "+f"(c[3])
        : "r"(a[0]), "r"(a[1]), "r"(a[2]), "r"(a[3]), "r"(b0), "r"(b1));
}

__device__ __forceinline__ void ldm4(uint32_t r[4], uint32_t addr) {
    asm volatile("ldmatrix.sync.aligned.m8n8.x4.shared.b16 {%0,%1,%2,%3}, [%4];"
        : "=r"(r[0]), "=r"(r[1]), "=r"(r[2]), "=r"(r[3]) : "r"(addr));
}

#define CP16(d, s)  asm volatile("cp.async.cg.shared.global [%0], [%1], 16;" :: "r"(d), "l"(s))
#define CPCOMMIT()  asm volatile("cp.async.commit_group;")
#define CPWAIT(n)   asm volatile("cp.async.wait_group %0;" :: "n"(n))

// ---------------------------------------------------------------------------
// Convert: tf32-round x and weights (fold 1/8 attention scale into Wq, bq)
// ---------------------------------------------------------------------------
__global__ __launch_bounds__(256) void convert_kernel(
    const float* __restrict__ x,  const float* __restrict__ Wq,
    const float* __restrict__ bq, const float* __restrict__ Wk,
    const float* __restrict__ Wv, const float* __restrict__ Wo)
{
    long long i = (long long)blockIdx.x * 256 + threadIdx.x;
    if (i < NX) { g_xt[i] = f2tf(x[i]); return; }
    i -= NX;
    if (i < NW) { g_wqt[i] = f2tf(Wq[i] * 0.125f); return; }
    i -= NW;
    if (i < NW) { g_wkt[i] = f2tf(Wk[i]); return; }
    i -= NW;
    if (i < NW) { g_wvt[i] = f2tf(Wv[i]); return; }
    i -= NW;
    if (i < D_ * D_) { g_wot[i] = f2tf(Wo[i]); return; }
    i -= D_ * D_;
    if (i < H_ * HD_) { g_bqs[i] = bq[i] * 0.125f; }
}

// ---------------------------------------------------------------------------
// QKV projection: 2-stage cp.async pipeline, ldmatrix A-frags.
// sA [row][k] stride 36; sB [k][n] stride 136 (bank = 8k+n: conflict-free).
// grid (32, 8, 3), 256 threads, warp tile 64x32.
// ---------------------------------------------------------------------------
#define QA_ST 36
#define QAW   (128 * QA_ST)      // 4608 words
#define QB_ST 136
#define QBW   (32 * QB_ST)       // 4352 words
#define QSTG  (QAW + QBW)        // 8960 words per stage
#define QKV_SMEM (2 * QSTG * 4)  // 71680 bytes

__global__ __launch_bounds__(256, 2) void qkv_kernel(
    const float* __restrict__ bk, const float* __restrict__ bv)
{
    extern __shared__ uint32_t dsm[];
    const int rt = blockIdx.x, hp = blockIdx.y, m = blockIdx.z;
    const uint32_t* W   = (m == 0) ? g_wqt : (m == 1) ? g_wkt : g_wvt;
    const float*    bias = (m == 0) ? g_bqs : (m == 1) ? bk : bv;
    uint32_t*       out = (m == 0) ? g_q : (m == 1) ? g_k : g_v;

    const int tid  = threadIdx.x;
    const int wid  = tid >> 5;
    const int lane = tid & 31;
    const int wm   = wid >> 2, wn = wid & 3;
    const int ql   = lane & 3, qr = lane >> 2;
    const int row0 = rt * 128;
    const int h0   = hp * 2;

    const uint32_t sm0 = (uint32_t)__cvta_generic_to_shared(dsm);
    const uint32_t aLane = ((wm * 64 + (lane & 15)) * QA_ST + (lane >> 4) * 4) * 4;

    float acc[4][4][4];
    #pragma unroll
    for (int mi = 0; mi < 4; mi++)
        #pragma unroll
        for (int ni = 0; ni < 4; ni++)
            #pragma unroll
            for (int c = 0; c < 4; c++) acc[mi][ni][c] = 0.f;

    // stage loader: chunk c into buffer s
    #define QKV_STAGE(c, s) {                                                  \
        uint32_t sb = sm0 + (s) * QSTG * 4;                                    \
        _Pragma("unroll")                                                      \
        for (int i = 0; i < 4; i++) {                                          \
            int g = i * 256 + tid; int row = g >> 3; int kg = (g & 7) * 4;     \
            CP16(sb + (row * QA_ST + kg) * 4,                                  \
                 &g_xt[(size_t)(row0 + row) * D_ + (c) * 32 + kg]);            \
        }                                                                      \
        _Pragma("unroll")                                                      \
        for (int i = 0; i < 4; i++) {                                          \
            int g = i * 256 + tid; int k = g >> 5; int n0 = (g & 31) * 4;      \
            CP16(sb + (QAW + k * QB_ST + n0) * 4,                              \
                 &W[((size_t)(h0 + (n0 >> 6)) * D_ + (c) * 32 + k) * HD_ + (n0 & 63)]); \
        }                                                                      \
    }

    QKV_STAGE(0, 0); CPCOMMIT();

    for (int c = 0; c < 32; c++) {
        if (c + 1 < 32) QKV_STAGE(c + 1, (c + 1) & 1);
        CPCOMMIT();
        CPWAIT(1);
        __syncthreads();

        const uint32_t sAb = sm0 + (c & 1) * QSTG * 4;
        const uint32_t* sB = dsm + (c & 1) * QSTG + QAW;

        #pragma unroll
        for (int kk = 0; kk < 4; kk++) {
            uint32_t a[4][4];
            #pragma unroll
            for (int mi = 0; mi < 4; mi++)
                ldm4(a[mi], sAb + aLane + (mi * 16 * QA_ST + kk * 8) * 4);
            uint32_t b0[4], b1[4];
            #pragma unroll
            for (int ni = 0; ni < 4; ni++) {
                int n = wn * 32 + ni * 8 + qr;
                b0[ni] = sB[(kk * 8 + ql) * QB_ST + n];
                b1[ni] = sB[(kk * 8 + ql + 4) * QB_ST + n];
            }
            #pragma unroll
            for (int mi = 0; mi < 4; mi++)
                #pragma unroll
                for (int ni = 0; ni < 4; ni++)
                    mma_tf32(acc[mi][ni], a[mi], b0[ni], b1[ni]);
        }
        __syncthreads();
    }

    // epilogue: tf32-rounded bits, layout [B,H,S,HD]
    #pragma unroll
    for (int mi = 0; mi < 4; mi++) {
        int row = row0 + wm * 64 + mi * 16 + qr;
        int bb  = row >> 11;
        int s   = row & (S_ - 1);
        #pragma unroll
        for (int ni = 0; ni < 4; ni++) {
            int cl = wn * 32 + ni * 8 + 2 * ql;
            int h  = h0 + (cl >> 6);
            int e  = cl & 63;
            float bv0 = bias[h * HD_ + e];
            float bv1 = bias[h * HD_ + e + 1];
            uint32_t* p0 = out + (((size_t)bb * H_ + h) * S_ + s) * HD_ + e;
            uint32_t* p1 = out + (((size_t)bb * H_ + h) * S_ + s + 8) * HD_ + e;
            p0[0] = f2tf(acc[mi][ni][0] + bv0); p0[1] = f2tf(acc[mi][ni][1] + bv1);
            p1[0] = f2tf(acc[mi][ni][2] + bv0); p1[1] = f2tf(acc[mi][ni][3] + bv1);
        }
    }
}

// ---------------------------------------------------------------------------
// Flash attention (causal): cp.async staging (raw tf32 bits), ldmatrix frags.
// 64 queries/block, 4 warps. grid (32 reversed, 32), 128 threads.
// ---------------------------------------------------------------------------
__global__ __launch_bounds__(128) void attn_kernel()
{
    __shared__ uint32_t sKP[64 * 68];   // Q -> K tile -> P (stride 68)
    __shared__ uint32_t sV[64 * 72];    // V tile (stride 72; bank 8k+n)

    const int qt = 31 - blockIdx.x;
    const int bh = blockIdx.y;
    const int b  = bh >> 4;
    const int h  = bh & 15;
    const int tid  = threadIdx.x;
    const int w    = tid >> 5;
    const int lane = tid & 31;
    const int qr   = lane >> 2;
    const int ql   = lane & 3;

    const uint32_t* Qb = g_q + (size_t)bh * S_ * HD_;
    const uint32_t* Kb = g_k + (size_t)bh * S_ * HD_;
    const uint32_t* Vb = g_v + (size_t)bh * S_ * HD_;

    const uint32_t skp_b = (uint32_t)__cvta_generic_to_shared(sKP);
    const uint32_t sv_b  = (uint32_t)__cvta_generic_to_shared(sV);
    const uint32_t aoff  = ((w * 16 + (lane & 15)) * 68 + (lane >> 4) * 4) * 4;
    const uint32_t koff  = ((lane & 15) * 68 + (lane >> 4) * 4) * 4;

    // ---- stage Q (pre-scaled), extract A fragments ----
    #pragma unroll
    for (int i = 0; i < 8; i++) {
        int g = i * 128 + tid;
        int row = g >> 4, c4 = (g & 15) * 4;
        CP16(skp_b + (row * 68 + c4) * 4, &Qb[(size_t)(qt * 64 + row) * HD_ + c4]);
    }
    CPCOMMIT(); CPWAIT(0);
    __syncthreads();

    uint32_t qa[8][4];
    #pragma unroll
    for (int kk = 0; kk < 8; kk++) ldm4(qa[kk], skp_b + aoff + kk * 32);

    float O[8][4];
    #pragma unroll
    for (int n = 0; n < 8; n++)
        #pragma unroll
        for (int c = 0; c < 4; c++) O[n][c] = 0.f;
    float m0 = -1e30f, m1 = -1e30f, l0 = 0.f, l1 = 0.f;

    for (int kt = 0; kt <= qt; kt++) {
        __syncthreads();                 // done with previous P / V
        const int j0 = kt * 64;
        #pragma unroll
        for (int i = 0; i < 8; i++) {
            int g = i * 128 + tid;
            int row = g >> 4, c4 = (g & 15) * 4;
            CP16(skp_b + (row * 68 + c4) * 4, &Kb[(size_t)(j0 + row) * HD_ + c4]);
            CP16(sv_b  + (row * 72 + c4) * 4, &Vb[(size_t)(j0 + row) * HD_ + c4]);
        }
        CPCOMMIT(); CPWAIT(0);
        __syncthreads();

        // ---- QK^T ----
        float sc[8][4];
        #pragma unroll
        for (int n = 0; n < 8; n++)
            #pragma unroll
            for (int c = 0; c < 4; c++) sc[n][c] = 0.f;
        #pragma unroll
        for (int kk = 0; kk < 8; kk++) {
            #pragma unroll
            for (int j = 0; j < 4; j++) {
                uint32_t kb[4];
                ldm4(kb, skp_b + koff + (j * 16 * 68) * 4 + kk * 32);
                mma_tf32(sc[2 * j],     qa[kk], kb[0], kb[2]);
                mma_tf32(sc[2 * j + 1], qa[kk], kb[1], kb[3]);
            }
        }

        if (kt == qt) {                  // causal mask on diagonal tile
            const int r0 = w * 16 + qr;
            #pragma unroll
            for (int n = 0; n < 8; n++) {
                int c = n * 8 + 2 * ql;
                if (c     > r0)     sc[n][0] = -1e30f;
                if (c + 1 > r0)     sc[n][1] = -1e30f;
                if (c     > r0 + 8) sc[n][2] = -1e30f;
                if (c + 1 > r0 + 8) sc[n][3] = -1e30f;
            }
        }

        // ---- online softmax ----
        float mt0 = -1e30f, mt1 = -1e30f;
        #pragma unroll
        for (int n = 0; n < 8; n++) {
            mt0 = fmaxf(mt0, fmaxf(sc[n][0], sc[n][1]));
            mt1 = fmaxf(mt1, fmaxf(sc[n][2], sc[n][3]));
        }
        mt0 = fmaxf(mt0, __shfl_xor_sync(0xffffffffu, mt0, 1));
        mt0 = fmaxf(mt0, __shfl_xor_sync(0xffffffffu, mt0, 2));
        mt1 = fmaxf(mt1, __shfl_xor_sync(0xffffffffu, mt1, 1));
        mt1 = fmaxf(mt1, __shfl_xor_sync(0xffffffffu, mt1, 2));
        float mn0 = fmaxf(m0, mt0), mn1 = fmaxf(m1, mt1);
        float cr0 = __expf(m0 - mn0), cr1 = __expf(m1 - mn1);
        m0 = mn0; m1 = mn1;
        #pragma unroll
        for (int n = 0; n < 8; n++) {
            O[n][0] *= cr0; O[n][1] *= cr0;
            O[n][2] *= cr1; O[n][3] *= cr1;
        }
        float s0 = 0.f, s1 = 0.f;
        #pragma unroll
        for (int n = 0; n < 8; n++) {
            sc[n][0] = __expf(sc[n][0] - mn0);
            sc[n][1] = __expf(sc[n][1] - mn0);
            sc[n][2] = __expf(sc[n][2] - mn1);
            sc[n][3] = __expf(sc[n][3] - mn1);
            s0 += sc[n][0] + sc[n][1];
            s1 += sc[n][2] + sc[n][3];
        }
        s0 += __shfl_xor_sync(0xffffffffu, s0, 1);
        s0 += __shfl_xor_sync(0xffffffffu, s0, 2);
        s1 += __shfl_xor_sync(0xffffffffu, s1, 1);
        s1 += __shfl_xor_sync(0xffffffffu, s1, 2);
        l0 = l0 * cr0 + s0;
        l1 = l1 * cr1 + s1;

        __syncthreads();                 // all warps done reading K
        #pragma unroll
        for (int n = 0; n < 8; n++) {    // write P (raw f32 bits = tf32-ok)
            int c = n * 8 + 2 * ql;
            uint32_t* d0 = &sKP[(w * 16 + qr) * 68 + c];
            uint32_t* d1 = &sKP[(w * 16 + qr + 8) * 68 + c];
            d0[0] = __float_as_uint(sc[n][0]); d0[1] = __float_as_uint(sc[n][1]);
            d1[0] = __float_as_uint(sc[n][2]); d1[1] = __float_as_uint(sc[n][3]);
        }
        __syncwarp();                    // PV reads only own warp's rows

        // ---- P @ V ----
        #pragma unroll
        for (int kk = 0; kk < 8; kk++) {
            uint32_t pa[4];
            ldm4(pa, skp_b + aoff + kk * 32);
            #pragma unroll
            for (int n = 0; n < 8; n++) {
                uint32_t vb0 = sV[(kk * 8 + ql) * 72 + n * 8 + qr];
                uint32_t vb1 = sV[(kk * 8 + ql + 4) * 72 + n * 8 + qr];
                mma_tf32(O[n], pa, vb0, vb1);
            }
        }
    }

    // ---- normalize + store tf32 bits to g_wv [B,S,H*HD] ----
    float inv0 = 1.f / l0, inv1 = 1.f / l1;
    int r0g = qt * 64 + w * 16 + qr;
    uint32_t* base0 = g_wv + ((size_t)b * S_ + r0g) * D_ + h * HD_;
    uint32_t* base1 = g_wv + ((size_t)b * S_ + r0g + 8) * D_ + h * HD_;
    #pragma unroll
    for (int n = 0; n < 8; n++) {
        int c = n * 8 + 2 * ql;
        base0[c]     = f2tf(O[n][0] * inv0);
        base0[c + 1] = f2tf(O[n][1] * inv0);
        base1[c]     = f2tf(O[n][2] * inv1);
        base1[c + 1] = f2tf(O[n][3] * inv1);
    }
}

// ---------------------------------------------------------------------------
// Output projection: 2-stage cp.async pipeline, ldmatrix A+B frags.
// sA, sB both [r][k] stride 36. grid (32, 8), 256 threads.
// ---------------------------------------------------------------------------
#define OA_ST 36
#define OAW   (128 * OA_ST)     // 4608 words
#define OSTG  (2 * OAW)         // 9216 words per stage
#define OP_SMEM (2 * OSTG * 4)  // 73728 bytes

__global__ __launch_bounds__(256, 2) void oproj_kernel(
    const float* __restrict__ bo, float* __restrict__ out)
{
    extern __shared__ uint32_t dsm[];
    const int rt = blockIdx.x, ct = blockIdx.y;

    const int tid  = threadIdx.x;
    const int wid  = tid >> 5;
    const int lane = tid & 31;
    const int wm   = wid >> 2, wn = wid & 3;
    const int ql   = lane & 3, qr = lane >> 2;
    const int row0 = rt * 128;
    const int col0 = ct * 128;

    const uint32_t sm0 = (uint32_t)__cvta_generic_to_shared(dsm);
    const uint32_t aLane = ((wm * 64 + (lane & 15)) * OA_ST + (lane >> 4) * 4) * 4;
    const uint32_t bLane = ((wn * 32 + (lane & 15)) * OA_ST + (lane >> 4) * 4) * 4;

    float acc[4][4][4];
    #pragma unroll
    for (int mi = 0; mi < 4; mi++)
        #pragma unroll
        for (int ni = 0; ni < 4; ni++)
            #pragma unroll
            for (int c = 0; c < 4; c++) acc[mi][ni][c] = 0.f;

    #define OP_STAGE(c, s) {                                                   \
        uint32_t sb = sm0 + (s) * OSTG * 4;                                    \
        _Pragma("unroll")                                                      \
        for (int i = 0; i < 4; i++) {                                          \
            int g = i * 256 + tid; int row = g >> 3; int kg = (g & 7) * 4;     \
            CP16(sb + (row * OA_ST + kg) * 4,                                  \
                 &g_wv[(size_t)(row0 + row) * D_ + (c) * 32 + kg]);            \
        }                                                                      \
        _Pragma("unroll")                                                      \
        for (int i = 0; i < 4; i++) {                                          \
            int g = i * 256 + tid; int n = g >> 3; int kg = (g & 7) * 4;       \
            CP16(sb + (OAW + n * OA_ST + kg) * 4,                              \
                 &g_wot[(size_t)(col0 + n) * D_ + (c) * 32 + kg]);             \
        }                                                                      \
    }

    OP_STAGE(0, 0); CPCOMMIT();

    for (int c = 0; c < 32; c++) {
        if (c + 1 < 32) OP_STAGE(c + 1, (c + 1) & 1);
        CPCOMMIT();
        CPWAIT(1);
        __syncthreads();

        const uint32_t sAb = sm0 + (c & 1) * OSTG * 4;
        const uint32_t sBb = sAb + OAW * 4;

        #pragma unroll
        for (int kk = 0; kk < 4; kk++) {
            uint32_t a[4][4];
            #pragma unroll
            for (int mi = 0; mi < 4; mi++)
                ldm4(a[mi], sAb + aLane + (mi * 16 * OA_ST + kk * 8) * 4);
            uint32_t bb[2][4];
            #pragma unroll
            for (int nj = 0; nj < 2; nj++)
                ldm4(bb[nj], sBb + bLane + (nj * 16 * OA_ST + kk * 8) * 4);
            #pragma unroll
            for (int mi = 0; mi < 4; mi++)
                #pragma unroll
                for (int nj = 0; nj < 2; nj++) {
                    mma_tf32(acc[mi][2 * nj],     a[mi], bb[nj][0], bb[nj][2]);
                    mma_tf32(acc[mi][2 * nj + 1], a[mi], bb[nj][1], bb[nj][3]);
                }
        }
        __syncthreads();
    }

    #pragma unroll
    for (int mi = 0; mi < 4; mi++) {
        int row = row0 + wm * 64 + mi * 16 + qr;
        #pragma unroll
        for (int ni = 0; ni < 4; ni++) {
            int col = col0 + wn * 32 + ni * 8 + 2 * ql;
            float bv0 = bo[col], bv1 = bo[col + 1];
            *(float2*)&out[(size_t)row * D_ + col] =
                make_float2(acc[mi][ni][0] + bv0, acc[mi][ni][1] + bv1);
            *(float2*)&out[(size_t)(row + 8) * D_ + col] =
                make_float2(acc[mi][ni][2] + bv0, acc[mi][ni][3] + bv1);
        }
    }
}

// ---------------------------------------------------------------------------
// Launch. metadata order: x, Wq, bq, Wk, bk, Wv, bv, Wo, bo
// ---------------------------------------------------------------------------
extern "C" void kernel_launch(void* const* d_in, const int* in_sizes, int n_in,
                              void* d_out, int out_size)
{
    const float* x  = (const float*)d_in[0];
    const float* Wq = (const float*)d_in[1];
    const float* bq = (const float*)d_in[2];
    const float* Wk = (const float*)d_in[3];
    const float* bk = (const float*)d_in[4];
    const float* Wv = (const float*)d_in[5];
    const float* bv = (const float*)d_in[6];
    const float* Wo = (const float*)d_in[7];
    const float* bo = (const float*)d_in[8];
    float* out = (float*)d_out;

    cudaFuncSetAttribute(qkv_kernel,  cudaFuncAttributeMaxDynamicSharedMemorySize, QKV_SMEM);
    cudaFuncSetAttribute(oproj_kernel, cudaFuncAttributeMaxDynamicSharedMemorySize, OP_SMEM);

    const long long ntot = (long long)NX + 4LL * NW + H_ * HD_;
    convert_kernel<<<(int)((ntot + 255) / 256), 256>>>(x, Wq, bq, Wk, Wv, Wo);

    dim3 g1(BS_ / 128, H_ / 2, 3);
    qkv_kernel<<<g1, 256, QKV_SMEM>>>(bk, bv);

    dim3 g2(S_ / 64, B_ * H_);
    attn_kernel<<<g2, 128>>>();

    dim3 g3(BS_ / 128, D_ / 128);
    oproj_kernel<<<g3, 256, OP_SMEM>>>(bo, out);
}

// round 9
// speedup vs baseline: 4.3724x; 1.0080x over previous
#include <cuda_runtime.h>
#include <stdint.h>

// Problem dims
#define B_  2
#define S_  2048
#define D_  1024
#define H_  16
#define HD_ 64
#define BS_ (B_ * S_)         // 4096
#define NX  (BS_ * D_)
#define NW  (H_ * D_ * HD_)

// tf32-bit scratch (device globals — allocation-guard safe)
__device__ uint32_t g_xt[NX];
__device__ uint32_t g_wqt[NW], g_wkt[NW], g_wvt[NW], g_wot[D_ * D_];
__device__ float    g_bqs[H_ * HD_];
__device__ uint32_t g_q[B_ * H_ * S_ * HD_];   // pre-scaled by 1/8
__device__ uint32_t g_k[B_ * H_ * S_ * HD_];
__device__ uint32_t g_v[B_ * H_ * S_ * HD_];
__device__ uint32_t g_wv[BS_ * D_];            // [B,S,H*HD] tf32 bits

__device__ __forceinline__ uint32_t f2tf(float f) {
    uint32_t u;
    asm("cvt.rna.tf32.f32 %0, %1;" : "=r"(u) : "f"(f));
    return u;
}

__device__ __forceinline__ void mma_tf32(float c[4], const uint32_t a[4],
                                         uint32_t b0, uint32_t b1) {
    asm volatile(
        "mma.sync.aligned.m16n8k8.row.col.f32.tf32.tf32.f32 "
        "{%0,%1,%2,%3}, {%4,%5,%6,%7}, {%8,%9}, {%0,%1,%2,%3};"
        : "+f"(c[0]), "+f"(c[1]), "+f"(c[2]), "+f"(c[3])
        : "r"(a[0]), "r"(a[1]), "r"(a[2]), "r"(a[3]), "r"(b0), "r"(b1));
}

__device__ __forceinline__ void ldm4(uint32_t r[4], uint32_t addr) {
    asm volatile("ldmatrix.sync.aligned.m8n8.x4.shared.b16 {%0,%1,%2,%3}, [%4];"
        : "=r"(r[0]), "=r"(r[1]), "=r"(r[2]), "=r"(r[3]) : "r"(addr));
}

#define CP16(d, s)  asm volatile("cp.async.cg.shared.global [%0], [%1], 16;" :: "r"(d), "l"(s))
#define CPCOMMIT()  asm volatile("cp.async.commit_group;")
#define CPWAIT(n)   asm volatile("cp.async.wait_group %0;" :: "n"(n))

// ---------------------------------------------------------------------------
// Convert: tf32-round x and weights (fold 1/8 scale into Wq, bq)
// ---------------------------------------------------------------------------
__global__ __launch_bounds__(256) void convert_kernel(
    const float* __restrict__ x,  const float* __restrict__ Wq,
    const float* __restrict__ bq, const float* __restrict__ Wk,
    const float* __restrict__ Wv, const float* __restrict__ Wo)
{
    long long i = (long long)blockIdx.x * 256 + threadIdx.x;
    if (i < NX) { g_xt[i] = f2tf(x[i]); return; }
    i -= NX;
    if (i < NW) { g_wqt[i] = f2tf(Wq[i] * 0.125f); return; }
    i -= NW;
    if (i < NW) { g_wkt[i] = f2tf(Wk[i]); return; }
    i -= NW;
    if (i < NW) { g_wvt[i] = f2tf(Wv[i]); return; }
    i -= NW;
    if (i < D_ * D_) { g_wot[i] = f2tf(Wo[i]); return; }
    i -= D_ * D_;
    if (i < H_ * HD_) { g_bqs[i] = bq[i] * 0.125f; }
}

// ---------------------------------------------------------------------------
// QKV projection: 3-buffer cp.async ring, prefill 2, issue c+2 after barrier.
// At iter c: buffer (c+2)%3 == (c-1)%3, freed by the barrier. Race-free.
// sA [row][k] stride 36; sB [k][n] stride 136. grid (32,8,3), 256 threads.
// ---------------------------------------------------------------------------
#define QA_ST 36
#define QAW   (128 * QA_ST)      // 4608 words
#define QB_ST 136
#define QBW   (32 * QB_ST)       // 4352 words
#define QSTG  (QAW + QBW)        // 8960 words/stage
#define QKV_SMEM (3 * QSTG * 4)  // 107520 bytes

__global__ __launch_bounds__(256, 1) void qkv_kernel(
    const float* __restrict__ bk, const float* __restrict__ bv)
{
    extern __shared__ uint32_t dsm[];
    const int rt = blockIdx.x, hp = blockIdx.y, m = blockIdx.z;
    const uint32_t* W    = (m == 0) ? g_wqt : (m == 1) ? g_wkt : g_wvt;
    const float*    bias = (m == 0) ? g_bqs : (m == 1) ? bk : bv;
    uint32_t*       out  = (m == 0) ? g_q : (m == 1) ? g_k : g_v;

    const int tid  = threadIdx.x;
    const int wid  = tid >> 5;
    const int lane = tid & 31;
    const int wm   = wid >> 2, wn = wid & 3;
    const int ql   = lane & 3, qr = lane >> 2;
    const int row0 = rt * 128;
    const int h0   = hp * 2;

    const uint32_t sm0 = (uint32_t)__cvta_generic_to_shared(dsm);
    const uint32_t aLane = ((wm * 64 + (lane & 15)) * QA_ST + (lane >> 4) * 4) * 4;

    float acc[4][4][4];
    #pragma unroll
    for (int mi = 0; mi < 4; mi++)
        #pragma unroll
        for (int ni = 0; ni < 4; ni++)
            #pragma unroll
            for (int c = 0; c < 4; c++) acc[mi][ni][c] = 0.f;

    #define QKV_STAGE(c, s) {                                                  \
        uint32_t sb = sm0 + (s) * QSTG * 4;                                    \
        _Pragma("unroll")                                                      \
        for (int i = 0; i < 4; i++) {                                          \
            int g = i * 256 + tid; int row = g >> 3; int kg = (g & 7) * 4;     \
            CP16(sb + (row * QA_ST + kg) * 4,                                  \
                 &g_xt[(size_t)(row0 + row) * D_ + (c) * 32 + kg]);            \
        }                                                                      \
        _Pragma("unroll")                                                      \
        for (int i = 0; i < 4; i++) {                                          \
            int g = i * 256 + tid; int k = g >> 5; int n0 = (g & 31) * 4;      \
            CP16(sb + (QAW + k * QB_ST + n0) * 4,                              \
                 &W[((size_t)(h0 + (n0 >> 6)) * D_ + (c) * 32 + k) * HD_ + (n0 & 63)]); \
        }                                                                      \
    }

    QKV_STAGE(0, 0); CPCOMMIT();
    QKV_STAGE(1, 1); CPCOMMIT();

    for (int c = 0; c < 32; c++) {
        const int cur = c % 3;
        CPWAIT(1);                       // stage c landed
        __syncthreads();                 // all threads done with compute c-1
        if (c + 2 < 32) { QKV_STAGE(c + 2, (c + 2) % 3); }
        CPCOMMIT();

        const uint32_t sAb = sm0 + cur * QSTG * 4;
        const uint32_t* sB = dsm + cur * QSTG + QAW;

        #pragma unroll
        for (int kk = 0; kk < 4; kk++) {
            uint32_t a[4][4];
            #pragma unroll
            for (int mi = 0; mi < 4; mi++)
                ldm4(a[mi], sAb + aLane + (mi * 16 * QA_ST + kk * 8) * 4);
            uint32_t b0[4], b1[4];
            #pragma unroll
            for (int ni = 0; ni < 4; ni++) {
                int n = wn * 32 + ni * 8 + qr;
                b0[ni] = sB[(kk * 8 + ql) * QB_ST + n];
                b1[ni] = sB[(kk * 8 + ql + 4) * QB_ST + n];
            }
            #pragma unroll
            for (int mi = 0; mi < 4; mi++)
                #pragma unroll
                for (int ni = 0; ni < 4; ni++)
                    mma_tf32(acc[mi][ni], a[mi], b0[ni], b1[ni]);
        }
    }

    #pragma unroll
    for (int mi = 0; mi < 4; mi++) {
        int row = row0 + wm * 64 + mi * 16 + qr;
        int bb  = row >> 11;
        int s   = row & (S_ - 1);
        #pragma unroll
        for (int ni = 0; ni < 4; ni++) {
            int cl = wn * 32 + ni * 8 + 2 * ql;
            int h  = h0 + (cl >> 6);
            int e  = cl & 63;
            float bv0 = bias[h * HD_ + e];
            float bv1 = bias[h * HD_ + e + 1];
            uint32_t* p0 = out + (((size_t)bb * H_ + h) * S_ + s) * HD_ + e;
            uint32_t* p1 = out + (((size_t)bb * H_ + h) * S_ + s + 8) * HD_ + e;
            p0[0] = f2tf(acc[mi][ni][0] + bv0); p0[1] = f2tf(acc[mi][ni][1] + bv1);
            p1[0] = f2tf(acc[mi][ni][2] + bv0); p1[1] = f2tf(acc[mi][ni][3] + bv1);
        }
    }
}

// ---------------------------------------------------------------------------
// Flash attention (causal): double-buffered K/V (stage kt+1 into the buffer
// freed by last iteration's compute — race-free), separate warp-local P.
// ONE barrier per K-tile. grid (32 rev, 32), 128 threads.
// ---------------------------------------------------------------------------
#define AK_W 4352                // 64*68
#define AV_W 4608                // 64*72
#define AP_OFF (2 * AK_W + 2 * AV_W)
#define ATT_SMEM ((AP_OFF + AK_W) * 4)

__global__ __launch_bounds__(128, 2) void attn_kernel()
{
    extern __shared__ uint32_t dsm[];
    uint32_t* sV = dsm + 2 * AK_W;
    uint32_t* sP = dsm + AP_OFF;

    const int qt = 31 - blockIdx.x;
    const int bh = blockIdx.y;
    const int b  = bh >> 4;
    const int h  = bh & 15;
    const int tid  = threadIdx.x;
    const int w    = tid >> 5;
    const int lane = tid & 31;
    const int qr   = lane >> 2;
    const int ql   = lane & 3;

    const uint32_t* Qb = g_q + (size_t)bh * S_ * HD_;
    const uint32_t* Kb = g_k + (size_t)bh * S_ * HD_;
    const uint32_t* Vb = g_v + (size_t)bh * S_ * HD_;

    const uint32_t sk_b = (uint32_t)__cvta_generic_to_shared(dsm);
    const uint32_t sp_b = sk_b + AP_OFF * 4;
    const uint32_t aoff = ((w * 16 + (lane & 15)) * 68 + (lane >> 4) * 4) * 4;
    const uint32_t koff = ((lane & 15) * 68 + (lane >> 4) * 4) * 4;

    // ---- stage Q (pre-scaled) into sP, extract A fragments ----
    #pragma unroll
    for (int i = 0; i < 8; i++) {
        int g = i * 128 + tid;
        int row = g >> 4, c4 = (g & 15) * 4;
        CP16(sp_b + (row * 68 + c4) * 4, &Qb[(size_t)(qt * 64 + row) * HD_ + c4]);
    }
    CPCOMMIT(); CPWAIT(0);
    __syncthreads();

    uint32_t qa[8][4];
    #pragma unroll
    for (int kk = 0; kk < 8; kk++) ldm4(qa[kk], sp_b + aoff + kk * 32);
    __syncthreads();                     // everyone has Q frags before P reuse

    #define ATT_STAGE(kt, s) {                                                 \
        _Pragma("unroll")                                                      \
        for (int i = 0; i < 8; i++) {                                          \
            int g = i * 128 + tid;                                             \
            int row = g >> 4, c4 = (g & 15) * 4;                               \
            CP16(sk_b + ((s) * AK_W + row * 68 + c4) * 4,                      \
                 &Kb[(size_t)((kt) * 64 + row) * HD_ + c4]);                   \
            CP16(sk_b + ((2 * AK_W + (s) * AV_W + row * 72 + c4)) * 4,         \
                 &Vb[(size_t)((kt) * 64 + row) * HD_ + c4]);                   \
        }                                                                      \
    }

    ATT_STAGE(0, 0); CPCOMMIT();

    float O[8][4];
    #pragma unroll
    for (int n = 0; n < 8; n++)
        #pragma unroll
        for (int c = 0; c < 4; c++) O[n][c] = 0.f;
    float m0 = -1e30f, m1 = -1e30f, l0 = 0.f, l1 = 0.f;

    for (int kt = 0; kt <= qt; kt++) {
        const int buf = kt & 1;
        CPWAIT(0);                       // tile kt landed
        __syncthreads();                 // all threads done with tile kt-1
        if (kt + 1 <= qt) { ATT_STAGE(kt + 1, buf ^ 1); }
        CPCOMMIT();

        // ---- QK^T ----
        const uint32_t kbase = sk_b + buf * AK_W * 4;
        float sc[8][4];
        #pragma unroll
        for (int n = 0; n < 8; n++)
            #pragma unroll
            for (int c = 0; c < 4; c++) sc[n][c] = 0.f;
        #pragma unroll
        for (int kk = 0; kk < 8; kk++) {
            #pragma unroll
            for (int j = 0; j < 4; j++) {
                uint32_t kb[4];
                ldm4(kb, kbase + koff + (j * 16 * 68) * 4 + kk * 32);
                mma_tf32(sc[2 * j],     qa[kk], kb[0], kb[2]);
                mma_tf32(sc[2 * j + 1], qa[kk], kb[1], kb[3]);
            }
        }

        if (kt == qt) {                  // causal mask on diagonal tile
            const int r0 = w * 16 + qr;
            #pragma unroll
            for (int n = 0; n < 8; n++) {
                int c = n * 8 + 2 * ql;
                if (c     > r0)     sc[n][0] = -1e30f;
                if (c + 1 > r0)     sc[n][1] = -1e30f;
                if (c     > r0 + 8) sc[n][2] = -1e30f;
                if (c + 1 > r0 + 8) sc[n][3] = -1e30f;
            }
        }

        // ---- online softmax ----
        float mt0 = -1e30f, mt1 = -1e30f;
        #pragma unroll
        for (int n = 0; n < 8; n++) {
            mt0 = fmaxf(mt0, fmaxf(sc[n][0], sc[n][1]));
            mt1 = fmaxf(mt1, fmaxf(sc[n][2], sc[n][3]));
        }
        mt0 = fmaxf(mt0, __shfl_xor_sync(0xffffffffu, mt0, 1));
        mt0 = fmaxf(mt0, __shfl_xor_sync(0xffffffffu, mt0, 2));
        mt1 = fmaxf(mt1, __shfl_xor_sync(0xffffffffu, mt1, 1));
        mt1 = fmaxf(mt1, __shfl_xor_sync(0xffffffffu, mt1, 2));
        float mn0 = fmaxf(m0, mt0), mn1 = fmaxf(m1, mt1);
        float cr0 = __expf(m0 - mn0), cr1 = __expf(m1 - mn1);
        m0 = mn0; m1 = mn1;
        #pragma unroll
        for (int n = 0; n < 8; n++) {
            O[n][0] *= cr0; O[n][1] *= cr0;
            O[n][2] *= cr1; O[n][3] *= cr1;
        }
        float s0 = 0.f, s1 = 0.f;
        #pragma unroll
        for (int n = 0; n < 8; n++) {
            sc[n][0] = __expf(sc[n][0] - mn0);
            sc[n][1] = __expf(sc[n][1] - mn0);
            sc[n][2] = __expf(sc[n][2] - mn1);
            sc[n][3] = __expf(sc[n][3] - mn1);
            s0 += sc[n][0] + sc[n][1];
            s1 += sc[n][2] + sc[n][3];
        }
        s0 += __shfl_xor_sync(0xffffffffu, s0, 1);
        s0 += __shfl_xor_sync(0xffffffffu, s0, 2);
        s1 += __shfl_xor_sync(0xffffffffu, s1, 1);
        s1 += __shfl_xor_sync(0xffffffffu, s1, 2);
        l0 = l0 * cr0 + s0;
        l1 = l1 * cr1 + s1;

        // ---- P (warp-local rows only) ----
        #pragma unroll
        for (int n = 0; n < 8; n++) {
            int c = n * 8 + 2 * ql;
            uint32_t* d0 = &sP[(w * 16 + qr) * 68 + c];
            uint32_t* d1 = &sP[(w * 16 + qr + 8) * 68 + c];
            d0[0] = __float_as_uint(sc[n][0]); d0[1] = __float_as_uint(sc[n][1]);
            d1[0] = __float_as_uint(sc[n][2]); d1[1] = __float_as_uint(sc[n][3]);
        }
        __syncwarp();

        // ---- P @ V ----
        const uint32_t* sVb = sV + buf * AV_W;
        #pragma unroll
        for (int kk = 0; kk < 8; kk++) {
            uint32_t pa[4];
            ldm4(pa, sp_b + aoff + kk * 32);
            #pragma unroll
            for (int n = 0; n < 8; n++) {
                uint32_t vb0 = sVb[(kk * 8 + ql) * 72 + n * 8 + qr];
                uint32_t vb1 = sVb[(kk * 8 + ql + 4) * 72 + n * 8 + qr];
                mma_tf32(O[n], pa, vb0, vb1);
            }
        }
    }

    // ---- normalize + store tf32 bits ----
    float inv0 = 1.f / l0, inv1 = 1.f / l1;
    int r0g = qt * 64 + w * 16 + qr;
    uint32_t* base0 = g_wv + ((size_t)b * S_ + r0g) * D_ + h * HD_;
    uint32_t* base1 = g_wv + ((size_t)b * S_ + r0g + 8) * D_ + h * HD_;
    #pragma unroll
    for (int n = 0; n < 8; n++) {
        int c = n * 8 + 2 * ql;
        base0[c]     = f2tf(O[n][0] * inv0);
        base0[c + 1] = f2tf(O[n][1] * inv0);
        base1[c]     = f2tf(O[n][2] * inv1);
        base1[c + 1] = f2tf(O[n][3] * inv1);
    }
}

// ---------------------------------------------------------------------------
// Output projection: 3-buffer ring (prefill 2, issue c+2), ldmatrix A+B.
// grid (32, 8), 256 threads.
// ---------------------------------------------------------------------------
#define OA_ST 36
#define OAW   (128 * OA_ST)     // 4608 words
#define OSTG  (2 * OAW)         // 9216 words/stage
#define OP_SMEM (3 * OSTG * 4)  // 110592 bytes

__global__ __launch_bounds__(256, 1) void oproj_kernel(
    const float* __restrict__ bo, float* __restrict__ out)
{
    extern __shared__ uint32_t dsm[];
    const int rt = blockIdx.x, ct = blockIdx.y;

    const int tid  = threadIdx.x;
    const int wid  = tid >> 5;
    const int lane = tid & 31;
    const int wm   = wid >> 2, wn = wid & 3;
    const int ql   = lane & 3, qr = lane >> 2;
    const int row0 = rt * 128;
    const int col0 = ct * 128;

    const uint32_t sm0 = (uint32_t)__cvta_generic_to_shared(dsm);
    const uint32_t aLane = ((wm * 64 + (lane & 15)) * OA_ST + (lane >> 4) * 4) * 4;
    const uint32_t bLane = ((wn * 32 + (lane & 15)) * OA_ST + (lane >> 4) * 4) * 4;

    float acc[4][4][4];
    #pragma unroll
    for (int mi = 0; mi < 4; mi++)
        #pragma unroll
        for (int ni = 0; ni < 4; ni++)
            #pragma unroll
            for (int c = 0; c < 4; c++) acc[mi][ni][c] = 0.f;

    #define OP_STAGE(c, s) {                                                   \
        uint32_t sb = sm0 + (s) * OSTG * 4;                                    \
        _Pragma("unroll")                                                      \
        for (int i = 0; i < 4; i++) {                                          \
            int g = i * 256 + tid; int row = g >> 3; int kg = (g & 7) * 4;     \
            CP16(sb + (row * OA_ST + kg) * 4,                                  \
                 &g_wv[(size_t)(row0 + row) * D_ + (c) * 32 + kg]);            \
        }                                                                      \
        _Pragma("unroll")                                                      \
        for (int i = 0; i < 4; i++) {                                          \
            int g = i * 256 + tid; int n = g >> 3; int kg = (g & 7) * 4;       \
            CP16(sb + (OAW + n * OA_ST + kg) * 4,                              \
                 &g_wot[(size_t)(col0 + n) * D_ + (c) * 32 + kg]);             \
        }                                                                      \
    }

    OP_STAGE(0, 0); CPCOMMIT();
    OP_STAGE(1, 1); CPCOMMIT();

    for (int c = 0; c < 32; c++) {
        const int cur = c % 3;
        CPWAIT(1);
        __syncthreads();
        if (c + 2 < 32) { OP_STAGE(c + 2, (c + 2) % 3); }
        CPCOMMIT();

        const uint32_t sAb = sm0 + cur * OSTG * 4;
        const uint32_t sBb = sAb + OAW * 4;

        #pragma unroll
        for (int kk = 0; kk < 4; kk++) {
            uint32_t a[4][4];
            #pragma unroll
            for (int mi = 0; mi < 4; mi++)
                ldm4(a[mi], sAb + aLane + (mi * 16 * OA_ST + kk * 8) * 4);
            uint32_t bb[2][4];
            #pragma unroll
            for (int nj = 0; nj < 2; nj++)
                ldm4(bb[nj], sBb + bLane + (nj * 16 * OA_ST + kk * 8) * 4);
            #pragma unroll
            for (int mi = 0; mi < 4; mi++)
                #pragma unroll
                for (int nj = 0; nj < 2; nj++) {
                    mma_tf32(acc[mi][2 * nj],     a[mi], bb[nj][0], bb[nj][2]);
                    mma_tf32(acc[mi][2 * nj + 1], a[mi], bb[nj][1], bb[nj][3]);
                }
        }
    }

    #pragma unroll
    for (int mi = 0; mi < 4; mi++) {
        int row = row0 + wm * 64 + mi * 16 + qr;
        #pragma unroll
        for (int ni = 0; ni < 4; ni++) {
            int col = col0 + wn * 32 + ni * 8 + 2 * ql;
            float bv0 = bo[col], bv1 = bo[col + 1];
            *(float2*)&out[(size_t)row * D_ + col] =
                make_float2(acc[mi][ni][0] + bv0, acc[mi][ni][1] + bv1);
            *(float2*)&out[(size_t)(row + 8) * D_ + col] =
                make_float2(acc[mi][ni][2] + bv0, acc[mi][ni][3] + bv1);
        }
    }
}

// ---------------------------------------------------------------------------
// Launch. metadata order: x, Wq, bq, Wk, bk, Wv, bv, Wo, bo
// ---------------------------------------------------------------------------
extern "C" void kernel_launch(void* const* d_in, const int* in_sizes, int n_in,
                              void* d_out, int out_size)
{
    const float* x  = (const float*)d_in[0];
    const float* Wq = (const float*)d_in[1];
    const float* bq = (const float*)d_in[2];
    const float* Wk = (const float*)d_in[3];
    const float* bk = (const float*)d_in[4];
    const float* Wv = (const float*)d_in[5];
    const float* bv = (const float*)d_in[6];
    const float* Wo = (const float*)d_in[7];
    const float* bo = (const float*)d_in[8];
    float* out = (float*)d_out;

    cudaFuncSetAttribute(qkv_kernel,   cudaFuncAttributeMaxDynamicSharedMemorySize, QKV_SMEM);
    cudaFuncSetAttribute(attn_kernel,  cudaFuncAttributeMaxDynamicSharedMemorySize, ATT_SMEM);
    cudaFuncSetAttribute(oproj_kernel, cudaFuncAttributeMaxDynamicSharedMemorySize, OP_SMEM);

    const long long ntot = (long long)NX + 4LL * NW + H_ * HD_;
    convert_kernel<<<(int)((ntot + 255) / 256), 256>>>(x, Wq, bq, Wk, Wv, Wo);

    dim3 g1(BS_ / 128, H_ / 2, 3);
    qkv_kernel<<<g1, 256, QKV_SMEM>>>(bk, bv);

    dim3 g2(S_ / 64, B_ * H_);
    attn_kernel<<<g2, 128, ATT_SMEM>>>();

    dim3 g3(BS_ / 128, D_ / 128);
    oproj_kernel<<<g3, 256, OP_SMEM>>>(bo, out);
}